// round 4
// baseline (speedup 1.0000x reference)
#include <cuda_runtime.h>
#include <math.h>

// Problem constants
#define BSZ   4
#define TT    2048
#define CC    2048
#define NH    16
#define NKV   4
#define HDIM  128
#define MROWS (BSZ * TT)       // 8192
#define KVC   (NKV * HDIM)     // 512

// Scratch (device globals: allocation is forbidden)
__device__ float g_Q[(size_t)MROWS * CC];    // 64 MB
__device__ float g_K[(size_t)MROWS * KVC];   // 16 MB
__device__ float g_V[(size_t)MROWS * KVC];   // 16 MB
__device__ float g_Y[(size_t)MROWS * CC];    // 64 MB

// ---------------------------------------------------------------------------
// SGEMM: C[M,N] = A[M,K] @ B[K,N], all row-major fp32.
// 128x128 block tile, BK=8, 256 threads, 8x8 per-thread microtile.
// Requires M%128==0, N%128==0, K%8==0 (true for all our shapes).
// ---------------------------------------------------------------------------
__global__ void __launch_bounds__(256) sgemm128(const float* __restrict__ A,
                                                const float* __restrict__ B,
                                                float* __restrict__ Cm,
                                                int N, int K) {
    __shared__ float As[8][128];
    __shared__ float Bs[8][132];

    const int tid = threadIdx.x;
    const int bm  = blockIdx.y * 128;
    const int bn  = blockIdx.x * 128;

    const int tx = tid & 15;   // 0..15 col group
    const int ty = tid >> 4;   // 0..15 row group

    // A tile load mapping: one float4 per thread per k-step
    const int arow = tid >> 1;
    const int acol = (tid & 1) * 4;
    // B tile load mapping
    const int brow = tid >> 5;
    const int bcol = (tid & 31) * 4;

    const float* Aptr = A + (size_t)(bm + arow) * K + acol;
    const float* Bptr = B + (size_t)brow * N + bn + bcol;

    float acc[8][8];
#pragma unroll
    for (int i = 0; i < 8; i++)
#pragma unroll
        for (int j = 0; j < 8; j++) acc[i][j] = 0.f;

    for (int k0 = 0; k0 < K; k0 += 8) {
        float4 av = *(const float4*)(Aptr + k0);
        float4 bv = *(const float4*)(Bptr + (size_t)k0 * N);
        As[acol + 0][arow] = av.x;
        As[acol + 1][arow] = av.y;
        As[acol + 2][arow] = av.z;
        As[acol + 3][arow] = av.w;
        *(float4*)&Bs[brow][bcol] = bv;
        __syncthreads();

#pragma unroll
        for (int kk = 0; kk < 8; kk++) {
            float a[8], b[8];
            *(float4*)&a[0] = *(const float4*)&As[kk][ty * 8];
            *(float4*)&a[4] = *(const float4*)&As[kk][ty * 8 + 4];
            *(float4*)&b[0] = *(const float4*)&Bs[kk][tx * 8];
            *(float4*)&b[4] = *(const float4*)&Bs[kk][tx * 8 + 4];
#pragma unroll
            for (int i = 0; i < 8; i++)
#pragma unroll
                for (int j = 0; j < 8; j++)
                    acc[i][j] += a[i] * b[j];
        }
        __syncthreads();
    }

#pragma unroll
    for (int i = 0; i < 8; i++) {
        size_t r = (size_t)(bm + ty * 8 + i);
        float4 v0 = make_float4(acc[i][0], acc[i][1], acc[i][2], acc[i][3]);
        float4 v1 = make_float4(acc[i][4], acc[i][5], acc[i][6], acc[i][7]);
        *(float4*)&Cm[r * N + bn + tx * 8]     = v0;
        *(float4*)&Cm[r * N + bn + tx * 8 + 4] = v1;
    }
}

// ---------------------------------------------------------------------------
// RoPE on Q [MROWS, NH, HDIM] and K [MROWS, NKV, HDIM].
// freqs_cis: [T, 64, 2] = (cos, sin) pairs.
// ---------------------------------------------------------------------------
__global__ void rope_kernel(float* __restrict__ Qb, float* __restrict__ Kb,
                            const float* __restrict__ fc) {
    int idx = blockIdx.x * blockDim.x + threadIdx.x;
    const int qpairs = MROWS * NH * (HDIM / 2);   // 8388608
    const int kpairs = MROWS * NKV * (HDIM / 2);  // 2097152
    if (idx < qpairs) {
        int p   = idx & 63;
        int h   = (idx >> 6) & (NH - 1);
        int row = idx >> 10;           // / (64*16)
        int t   = row & (TT - 1);
        float2 cs = ((const float2*)fc)[t * 64 + p];
        float2* ptr = (float2*)(Qb + (size_t)row * CC + h * HDIM) + p;
        float2 v = *ptr;
        *ptr = make_float2(v.x * cs.x - v.y * cs.y, v.x * cs.y + v.y * cs.x);
    } else if (idx < qpairs + kpairs) {
        int j   = idx - qpairs;
        int p   = j & 63;
        int h   = (j >> 6) & (NKV - 1);
        int row = j >> 8;              // / (64*4)
        int t   = row & (TT - 1);
        float2 cs = ((const float2*)fc)[t * 64 + p];
        float2* ptr = (float2*)(Kb + (size_t)row * KVC + h * HDIM) + p;
        float2 v = *ptr;
        *ptr = make_float2(v.x * cs.x - v.y * cs.y, v.x * cs.y + v.y * cs.x);
    }
}

// ---------------------------------------------------------------------------
// Flash attention (fp32, causal, GQA). BM=BN=64, HD=128, 256 threads.
// grid: (T/64, B*NH). Each thread: 4x4 S microtile, 4x8 O microtile.
// Row reductions via 16-lane shfl (lanes [0,16) / [16,32) of each warp).
// ---------------------------------------------------------------------------
#define FL_QS 0                      // QsT [128][68]
#define FL_KS (128 * 68)             // KsT [128][68]
#define FL_VS (FL_KS + 128 * 68)     // Vs  [64][132]
#define FL_PS (FL_VS + 64 * 132)     // Ps  [64][68]
#define FL_SMEM_FLOATS (FL_PS + 64 * 68)
#define FL_SMEM_BYTES  (FL_SMEM_FLOATS * 4)   // 120832

__global__ void __launch_bounds__(256) flash_kernel(const float* __restrict__ Q,
                                                    const float* __restrict__ Kb,
                                                    const float* __restrict__ Vb,
                                                    float* __restrict__ Y) {
    extern __shared__ float sm[];
    float* QsT = sm + FL_QS;
    float* KsT = sm + FL_KS;
    float* Vs  = sm + FL_VS;
    float* Ps  = sm + FL_PS;

    const int tid = threadIdx.x;
    const int qb  = blockIdx.x;            // query tile index
    const int bh  = blockIdx.y;
    const int b   = bh / NH;
    const int h   = bh % NH;
    const int g   = h >> 2;                // kv head (N_REP = 4)

    const float* qsrc0 = Q  + (size_t)b * TT * CC  + (size_t)h * HDIM;
    const float* ksrc0 = Kb + (size_t)b * TT * KVC + (size_t)g * HDIM;
    const float* vsrc0 = Vb + (size_t)b * TT * KVC + (size_t)g * HDIM;

    // Load Q tile transposed: QsT[d][r]
    {
        int r = tid >> 2, f = tid & 3;
        const float* src = qsrc0 + (size_t)(qb * 64 + r) * CC;
#pragma unroll
        for (int q = 0; q < 8; q++) {
            int d = (f * 8 + q) * 4;
            float4 v = *(const float4*)(src + d);
            QsT[(d + 0) * 68 + r] = v.x;
            QsT[(d + 1) * 68 + r] = v.y;
            QsT[(d + 2) * 68 + r] = v.z;
            QsT[(d + 3) * 68 + r] = v.w;
        }
    }

    const int rg = tid >> 4;     // 0..15
    const int cg = tid & 15;     // 0..15
    const int r0 = rg * 4;
    const int c0 = cg * 4;
    const int oc0 = cg * 8;

    float m_i[4], l_i[4], o[4][8];
#pragma unroll
    for (int i = 0; i < 4; i++) {
        m_i[i] = -1e30f; l_i[i] = 0.f;
#pragma unroll
        for (int j = 0; j < 8; j++) o[i][j] = 0.f;
    }

    const float scale = 0.08838834764831845f;  // 1/sqrt(128)
    const int ntiles = qb + 1;

    for (int kt = 0; kt < ntiles; kt++) {
        __syncthreads();  // protect K/V/P from previous iteration's readers
        // Load K tile (transposed) and V tile (row-major)
        {
            int r = tid >> 2, f = tid & 3;
            const float* ks = ksrc0 + (size_t)(kt * 64 + r) * KVC;
            const float* vs = vsrc0 + (size_t)(kt * 64 + r) * KVC;
#pragma unroll
            for (int q = 0; q < 8; q++) {
                int d = (f * 8 + q) * 4;
                float4 kv = *(const float4*)(ks + d);
                KsT[(d + 0) * 68 + r] = kv.x;
                KsT[(d + 1) * 68 + r] = kv.y;
                KsT[(d + 2) * 68 + r] = kv.z;
                KsT[(d + 3) * 68 + r] = kv.w;
                *(float4*)&Vs[r * 132 + d] = *(const float4*)(vs + d);
            }
        }
        __syncthreads();

        // S = Q @ K^T (4x4 per thread)
        float s[4][4];
#pragma unroll
        for (int i = 0; i < 4; i++)
#pragma unroll
            for (int j = 0; j < 4; j++) s[i][j] = 0.f;

#pragma unroll 4
        for (int d = 0; d < HDIM; d++) {
            float4 a4 = *(const float4*)&QsT[d * 68 + r0];
            float4 b4 = *(const float4*)&KsT[d * 68 + c0];
            float av[4] = {a4.x, a4.y, a4.z, a4.w};
            float bv[4] = {b4.x, b4.y, b4.z, b4.w};
#pragma unroll
            for (int i = 0; i < 4; i++)
#pragma unroll
                for (int j = 0; j < 4; j++)
                    s[i][j] += av[i] * bv[j];
        }

        // Scale + causal mask
        const int qrow0 = qb * 64 + r0;
        const int kcol0 = kt * 64 + c0;
#pragma unroll
        for (int i = 0; i < 4; i++)
#pragma unroll
            for (int j = 0; j < 4; j++) {
                s[i][j] *= scale;
                if (kcol0 + j > qrow0 + i) s[i][j] = -1e30f;
            }

        // Online softmax update (per row, reduce across 16 col-lanes)
#pragma unroll
        for (int i = 0; i < 4; i++) {
            float mx = fmaxf(fmaxf(s[i][0], s[i][1]), fmaxf(s[i][2], s[i][3]));
#pragma unroll
            for (int off = 1; off < 16; off <<= 1)
                mx = fmaxf(mx, __shfl_xor_sync(0xffffffffu, mx, off));
            float m_new = fmaxf(m_i[i], mx);
            float corr  = __expf(m_i[i] - m_new);
            float psum = 0.f;
#pragma unroll
            for (int j = 0; j < 4; j++) {
                float p = __expf(s[i][j] - m_new);
                s[i][j] = p;
                psum += p;
            }
#pragma unroll
            for (int off = 1; off < 16; off <<= 1)
                psum += __shfl_xor_sync(0xffffffffu, psum, off);
            l_i[i] = l_i[i] * corr + psum;
            m_i[i] = m_new;
#pragma unroll
            for (int j = 0; j < 8; j++) o[i][j] *= corr;
        }

        // Stage P to smem for the PV GEMM
#pragma unroll
        for (int i = 0; i < 4; i++)
#pragma unroll
            for (int j = 0; j < 4; j++)
                Ps[(r0 + i) * 68 + c0 + j] = s[i][j];
        __syncthreads();

        // O += P @ V  (4 rows x 8 cols per thread)
#pragma unroll 4
        for (int j = 0; j < 64; j++) {
            float p0 = Ps[(r0 + 0) * 68 + j];
            float p1 = Ps[(r0 + 1) * 68 + j];
            float p2 = Ps[(r0 + 2) * 68 + j];
            float p3 = Ps[(r0 + 3) * 68 + j];
            float4 v0 = *(const float4*)&Vs[j * 132 + oc0];
            float4 v1 = *(const float4*)&Vs[j * 132 + oc0 + 4];
            float vv[8] = {v0.x, v0.y, v0.z, v0.w, v1.x, v1.y, v1.z, v1.w};
#pragma unroll
            for (int c = 0; c < 8; c++) {
                o[0][c] += p0 * vv[c];
                o[1][c] += p1 * vv[c];
                o[2][c] += p2 * vv[c];
                o[3][c] += p3 * vv[c];
            }
        }
    }

    // Epilogue: normalize and write Y[b, t, h*HD + oc0 .. +7]
#pragma unroll
    for (int i = 0; i < 4; i++) {
        float inv = 1.f / l_i[i];
        size_t row = (size_t)b * TT + (size_t)(qb * 64 + r0 + i);
        float* dst = Y + row * CC + h * HDIM + oc0;
        float4 w0 = make_float4(o[i][0] * inv, o[i][1] * inv,
                                o[i][2] * inv, o[i][3] * inv);
        float4 w1 = make_float4(o[i][4] * inv, o[i][5] * inv,
                                o[i][6] * inv, o[i][7] * inv);
        *(float4*)dst       = w0;
        *(float4*)(dst + 4) = w1;
    }
}

// ---------------------------------------------------------------------------
extern "C" void kernel_launch(void* const* d_in, const int* in_sizes, int n_in,
                              void* d_out, int out_size) {
    (void)in_sizes; (void)n_in; (void)out_size;
    const float* x  = (const float*)d_in[0];
    const float* fc = (const float*)d_in[1];
    const float* wq = (const float*)d_in[2];
    const float* wk = (const float*)d_in[3];
    const float* wv = (const float*)d_in[4];
    const float* wo = (const float*)d_in[5];
    float* out = (float*)d_out;

    float *Qp, *Kp, *Vp, *Yp;
    cudaGetSymbolAddress((void**)&Qp, g_Q);
    cudaGetSymbolAddress((void**)&Kp, g_K);
    cudaGetSymbolAddress((void**)&Vp, g_V);
    cudaGetSymbolAddress((void**)&Yp, g_Y);

    dim3 blk(256);

    // QKV projections
    sgemm128<<<dim3(CC / 128,  MROWS / 128), blk>>>(x, wq, Qp, CC,  CC);
    sgemm128<<<dim3(KVC / 128, MROWS / 128), blk>>>(x, wk, Kp, KVC, CC);
    sgemm128<<<dim3(KVC / 128, MROWS / 128), blk>>>(x, wv, Vp, KVC, CC);

    // RoPE on Q and K
    int total_pairs = MROWS * NH * (HDIM / 2) + MROWS * NKV * (HDIM / 2);
    rope_kernel<<<(total_pairs + 255) / 256, 256>>>(Qp, Kp, fc);

    // Flash attention
    cudaFuncSetAttribute(flash_kernel, cudaFuncAttributeMaxDynamicSharedMemorySize,
                         FL_SMEM_BYTES);
    flash_kernel<<<dim3(TT / 64, BSZ * NH), blk, FL_SMEM_BYTES>>>(Qp, Kp, Vp, Yp);

    // Output projection
    sgemm128<<<dim3(CC / 128, MROWS / 128), blk>>>(Yp, wo, out, CC, CC);
}